// round 15
// baseline (speedup 1.0000x reference)
#include <cuda_runtime.h>
#include <math.h>
#include <stdint.h>

// Problem constants
#define BB 4
#define TT 1024
#define HH 1024
#define NHEAD 16
#define HDIM 64
#define ROWS (BB*TT)          // 4096

// ---------------- scratch (no allocs allowed) ----------------
__device__ float g_hp  [ROWS*HH];       // LN out, A-fragment-order (KC=32)
__device__ float g_q   [ROWS*HH];       // [b][head][t][d]
__device__ float g_k   [ROWS*HH];
__device__ float g_v   [ROWS*HH];
__device__ float g_x1  [ROWS*HH];       // x + attn out (row-major)
__device__ float g_m1  [ROWS*4*HH];     // gelu out, A-fragment-order (KC=128)
__device__ float g_wqkv[3*HH*HH];       // Wq|Wk|Wv, B-fragment-order, N=3072
__device__ float g_w1  [HH*4*HH];
__device__ float g_w2  [4*HH*HH];

// ---------------- helpers ----------------
__device__ __forceinline__ float tf32r(float x) {
    uint32_t r;
    asm("cvt.rna.tf32.f32 %0, %1;" : "=r"(r) : "f"(x));
    return __uint_as_float(r);
}
__device__ __forceinline__ uint32_t smem_u32(const void* p) {
    uint32_t a;
    asm("{ .reg .u64 t; cvta.to.shared.u64 t, %1; cvt.u32.u64 %0, t; }"
        : "=r"(a) : "l"(p));
    return a;
}
__device__ __forceinline__ void mma8(float* d, const uint32_t* a, const uint32_t* b) {
    asm volatile(
        "mma.sync.aligned.m16n8k8.row.col.f32.tf32.tf32.f32 "
        "{%0,%1,%2,%3}, {%4,%5,%6,%7}, {%8,%9}, {%0,%1,%2,%3};"
        : "+f"(d[0]), "+f"(d[1]), "+f"(d[2]), "+f"(d[3])
        : "r"(a[0]), "r"(a[1]), "r"(a[2]), "r"(a[3]), "r"(b[0]), "r"(b[1]));
}
#define CP16(dst, src) \
    asm volatile("cp.async.cg.shared.global [%0], [%1], 16;" :: "r"(dst), "l"(src))
#define CP_COMMIT() asm volatile("cp.async.commit_group;")
#define CP_WAIT2()  asm volatile("cp.async.wait_group 2;")

// ============ fused weight prep: all 5 weights -> B-fragment-order + tf32 ============
__global__ __launch_bounds__(256) void prep_all(
    const float* __restrict__ Wq, const float* __restrict__ Wk,
    const float* __restrict__ Wv, const float* __restrict__ W1,
    const float* __restrict__ W2,
    float* __restrict__ wqkv, float* __restrict__ w1, float* __restrict__ w2)
{
    __shared__ float s[32 * 132];
    const int t = threadIdx.x, blk = blockIdx.x;
    const float* W; float* out; int N, kc, nb;
    if (blk < 768) {
        int w = blk >> 8, r = blk & 255;
        nb = r >> 5; kc = r & 31; N = HH;
        W = (w == 0) ? Wq : (w == 1) ? Wk : Wv;
        out = wqkv + ((size_t)(w * 8 + nb) * 32 + kc) * 4096;
    } else if (blk < 1792) {
        int r = blk - 768;
        nb = r >> 5; kc = r & 31; N = 4 * HH;
        W = W1; out = w1 + ((size_t)nb * 32 + kc) * 4096;
    } else {
        int r = blk - 1792;
        nb = r >> 7; kc = r & 127; N = HH;
        W = W2; out = w2 + ((size_t)nb * 128 + kc) * 4096;
    }
    const float* Wg = W + (size_t)(kc * 32) * N + nb * 128;
    #pragma unroll
    for (int i = 0; i < 4; i++) {
        int fl = t + i * 256;
        int r = fl >> 5, c4 = (fl & 31) << 2;
        float4 v = *(const float4*)(Wg + (size_t)r * N + c4);
        s[r * 132 + c4 + 0] = v.x; s[r * 132 + c4 + 1] = v.y;
        s[r * 132 + c4 + 2] = v.z; s[r * 132 + c4 + 3] = v.w;
    }
    __syncthreads();
    float* o = out + t * 16;
    #pragma unroll
    for (int j4 = 0; j4 < 4; j4++) {
        float4 v; float* vp = (float*)&v;
        #pragma unroll
        for (int e = 0; e < 4; e++) {
            int f = t * 16 + j4 * 4 + e;
            int nt = f >> 8, ks = (f >> 6) & 3, ln = (f >> 1) & 31, rg = f & 1;
            int k3 = rg * 4 + (ln & 3);
            int nl = nt * 8 + ((ln >> 4) << 2) + ((ln >> 2) & 3);
            vp[e] = tf32r(s[(ks * 8 + k3) * 132 + nl]);
        }
        *(float4*)(o + j4 * 4) = v;
    }
}

// ---------------- LayerNorm -> A-fragment-order output (KC=32) ----------------
__global__ __launch_bounds__(256) void ln_kernel(
    const float* __restrict__ x, const float* __restrict__ g,
    const float* __restrict__ b, float* __restrict__ out)
{
    __shared__ float red[8];
    const int row = blockIdx.x, tid = threadIdx.x;
    const float* xr = x + (size_t)row * HH;
    float4 v = *(const float4*)(xr + tid * 4);

    float s = v.x + v.y + v.z + v.w;
    #pragma unroll
    for (int o = 16; o > 0; o >>= 1) s += __shfl_xor_sync(0xffffffffu, s, o);
    if ((tid & 31) == 0) red[tid >> 5] = s;
    __syncthreads();
    float tot = red[0]+red[1]+red[2]+red[3]+red[4]+red[5]+red[6]+red[7];
    const float mu = tot * (1.0f / HH);

    float dx = v.x - mu, dy = v.y - mu, dz = v.z - mu, dw = v.w - mu;
    float ss = dx*dx + dy*dy + dz*dz + dw*dw;
    #pragma unroll
    for (int o = 16; o > 0; o >>= 1) ss += __shfl_xor_sync(0xffffffffu, ss, o);
    __syncthreads();
    if ((tid & 31) == 0) red[tid >> 5] = ss;
    __syncthreads();
    float tot2 = red[0]+red[1]+red[2]+red[3]+red[4]+red[5]+red[6]+red[7];
    const float rs = rsqrtf(tot2 * (1.0f / HH) + 1e-5f);

    float4 gv = *(const float4*)(g + tid * 4);
    float4 bv = *(const float4*)(b + tid * 4);
    float o0 = dx * rs * gv.x + bv.x;
    float o1 = dy * rs * gv.y + bv.y;
    float o2 = dz * rs * gv.z + bv.z;
    float o3 = dw * rs * gv.w + bv.w;

    const int mb = row >> 7, mt = (row >> 4) & 7, hi = (row >> 3) & 1, gg = row & 7;
    const int kc = tid >> 3, ks = (tid >> 1) & 3, chi = tid & 1;
    float* op = out + ((size_t)(mb * 32 + kc)) * 4096
              + (mt * 4 + ks) * 128 + gg * 16 + hi + 2 * chi;
    op[0]  = tf32r(o0);
    op[4]  = tf32r(o1);
    op[8]  = tf32r(o2);
    op[12] = tf32r(o3);
}

// ===== tf32 mma.sync GEMM: 256x128 CTA, 8 warps of 64x64, 4-stage cp.async =====
enum { EPI_QKV = 0, EPI_GELU = 1, EPI_RES = 2 };

#define STG_F 12288                       // floats per stage: A 8192 + B 4096
#define GEMM_SMEM (4 * STG_F * 4)         // 192 KB

template <int EPI>
__global__ __launch_bounds__(256, 1) void gemm_mma(
    const float* __restrict__ Ap, const float* __restrict__ Bp,
    const float* __restrict__ bias, const float* __restrict__ bias2,
    const float* __restrict__ bias3, const float* __restrict__ resid,
    float* __restrict__ C, float* __restrict__ C2, float* __restrict__ C3,
    int N, int Kd)
{
    extern __shared__ __align__(16) float smem[];   // [4][STG_F]
    const int tid = threadIdx.x, lane = tid & 31, wid = tid >> 5;
    const int wm = wid & 3, wn = wid >> 2;          // 4 x 2 warps, 64x64 tiles
    const int gl = lane >> 2, cl = lane & 3;
    const int bn = blockIdx.x * 128, bm = blockIdx.y * 256;
    const int KC = Kd >> 5;
    const float* Ach = Ap + (size_t)(2 * blockIdx.y) * KC * 4096;  // two row-blocks
    const float* Bch = Bp + (size_t)blockIdx.x * KC * 4096;
    const uint32_t sb = smem_u32(smem);

    float acc[4][8][4];
    #pragma unroll
    for (int mi = 0; mi < 4; mi++)
        #pragma unroll
        for (int ni = 0; ni < 8; ni++)
            #pragma unroll
            for (int r = 0; r < 4; r++) acc[mi][ni][r] = 0.f;

    auto issue = [&](int st, int kc) {
        if (kc < KC) {
            const float* A0 = Ach + (size_t)kc * 4096;                 // rows 0-127
            const float* A1 = Ach + (size_t)(KC + kc) * 4096;          // rows 128-255
            const float* Bs = Bch + (size_t)kc * 4096;
            uint32_t da = sb + st * (STG_F * 4);
            #pragma unroll
            for (int i = 0; i < 4; i++) {
                int fl = (tid + i * 256) * 4;
                CP16(da + fl * 4,         A0 + fl);
                CP16(da + 16384 + fl * 4, A1 + fl);
                CP16(da + 32768 + fl * 4, Bs + fl);
            }
        }
        CP_COMMIT();
    };

    issue(0, 0);
    issue(1, 1);
    issue(2, 2);
    const int blkA = wm >> 1;                    // which 128-row A block
    for (int kc = 0; kc < KC; kc++) {
        CP_WAIT2();
        __syncthreads();
        issue((kc + 3) & 3, kc + 3);
        const float* sA = smem + (kc & 3) * STG_F + blkA * 4096;
        const float* sB = smem + (kc & 3) * STG_F + 8192;
        #pragma unroll
        for (int ks = 0; ks < 4; ks++) {
            uint32_t af[4][4];
            uint32_t bf[8][2];
            #pragma unroll
            for (int mi = 0; mi < 4; mi++) {
                int mt = ((wm & 1) << 2) + mi;
                *(uint4*)af[mi] =
                    *(const uint4*)&sA[((mt << 2) + ks) * 128 + (lane << 2)];
            }
            #pragma unroll
            for (int ni = 0; ni < 8; ni++) {
                int nt = wn * 8 + ni;
                *(uint2*)bf[ni] =
                    *(const uint2*)&sB[((nt << 2) + ks) * 64 + (lane << 1)];
            }
            #pragma unroll
            for (int mi = 0; mi < 4; mi++)
                #pragma unroll
                for (int ni = 0; ni < 8; ni++)
                    mma8(acc[mi][ni], af[mi], bf[ni]);
        }
    }

    // ---- epilogue ----
    const float* bs = bias;
    float* Cd = C;
    int bnl = bn;
    if (EPI == EPI_QKV) {
        const int which = bn >> 10;
        bs  = (which == 0) ? bias : (which == 1) ? bias2 : bias3;
        Cd  = (which == 0) ? C    : (which == 1) ? C2    : C3;
        bnl = bn & 1023;
    }
    #pragma unroll
    for (int mi = 0; mi < 4; mi++) {
        const int r0 = bm + wm * 64 + mi * 16 + gl;   // second half row r0+8
        #pragma unroll
        for (int ni = 0; ni < 8; ni++) {
            const int colw = wn * 64 + ni * 8 + (cl << 1);
            const int col = (EPI == EPI_QKV) ? (bnl + colw) : (bn + colw);
            const float bx = __ldg(&bs[col]);
            const float by = __ldg(&bs[col + 1]);
            float v00 = acc[mi][ni][0] + bx, v01 = acc[mi][ni][1] + by;
            float v10 = acc[mi][ni][2] + bx, v11 = acc[mi][ni][3] + by;
            if (EPI == EPI_QKV) {
                const int head = col >> 6, d0 = col & 63;
                #pragma unroll
                for (int hh2 = 0; hh2 < 2; hh2++) {
                    const int row = r0 + hh2 * 8;
                    float* Cp = Cd + ((size_t)((row >> 10) * NHEAD + head)) * (TT * HDIM)
                                   + (size_t)(row & (TT - 1)) * HDIM + d0;
                    float2 o = hh2 ? make_float2(v10, v11) : make_float2(v00, v01);
                    *(float2*)Cp = o;
                }
            } else if (EPI == EPI_GELU) {
                float t00 = 0.5f * v00 * (1.0f + erff(v00 * 0.70710678118654752f));
                float t01 = 0.5f * v01 * (1.0f + erff(v01 * 0.70710678118654752f));
                float t10 = 0.5f * v10 * (1.0f + erff(v10 * 0.70710678118654752f));
                float t11 = 0.5f * v11 * (1.0f + erff(v11 * 0.70710678118654752f));
                size_t idx = ((size_t)((r0 >> 7) * 128 + (col >> 5))) * 4096
                           + ((((r0 >> 4) & 7) << 2) + ((col >> 3) & 3)) * 128
                           + (((r0 & 7) << 2) + (col & 3)) * 4
                           + ((col >> 2) & 1) * 2;
                *(float2*)(Cd + idx)     = make_float2(tf32r(t00), tf32r(t10));
                *(float2*)(Cd + idx + 4) = make_float2(tf32r(t01), tf32r(t11));
            } else {
                float2 ra = *(const float2*)(resid + (size_t)r0 * N + col);
                float2 rb = *(const float2*)(resid + (size_t)(r0 + 8) * N + col);
                *(float2*)(Cd + (size_t)r0 * N + col) =
                    make_float2(v00 + ra.x, v01 + ra.y);
                *(float2*)(Cd + (size_t)(r0 + 8) * N + col) =
                    make_float2(v10 + rb.x, v11 + rb.y);
            }
        }
    }
}

// ======== Tensor-core attention: 4 warps x 16 q-rows, register softmax ========
#define AST 68
#define VST 72
#define ATTN_SMEM (size_t)((64*AST + 64*VST + 64*AST) * sizeof(float))

__global__ __launch_bounds__(128, 3) void attn_tc(
    const float* __restrict__ q, const float* __restrict__ k,
    const float* __restrict__ v, const float* __restrict__ x,
    float* __restrict__ x1)
{
    extern __shared__ __align__(16) float sm[];
    float* Ks = sm;                 // 64 x AST (also Q staging)
    float* Vs = Ks + 64 * AST;      // 64 x VST
    float* Ps = Vs + 64 * VST;      // 64 x AST (P; vsum scratch after loop)

    const int tid = threadIdx.x, lane = tid & 31, w = tid >> 5;
    const int gl = lane >> 2, cl = lane & 3;
    const int qt = (int)gridDim.x - 1 - (int)blockIdx.x;   // heavy tiles first
    const int head = blockIdx.y, b = blockIdx.z;
    const int qg0 = qt * 64;

    const float* Qg = q + (size_t)((b * NHEAD + head) * TT + qg0) * HDIM;
    const float* Kg = k + (size_t)(b * NHEAD + head) * TT * HDIM;
    const float* Vg = v + (size_t)(b * NHEAD + head) * TT * HDIM;

    for (int i = tid; i < 64 * 16; i += 128) {
        int r = i >> 4, c4 = (i & 15) << 2;
        *(float4*)&Ks[r * AST + c4] = *(const float4*)&Qg[r * 64 + c4];
    }
    __syncthreads();
    uint32_t qf[8][4];
    #pragma unroll
    for (int ks = 0; ks < 8; ks++) {
        qf[ks][0] = __float_as_uint(tf32r(Ks[(w*16+gl  ) * AST + ks*8 + cl    ]));
        qf[ks][1] = __float_as_uint(tf32r(Ks[(w*16+gl+8) * AST + ks*8 + cl    ]));
        qf[ks][2] = __float_as_uint(tf32r(Ks[(w*16+gl  ) * AST + ks*8 + cl + 4]));
        qf[ks][3] = __float_as_uint(tf32r(Ks[(w*16+gl+8) * AST + ks*8 + cl + 4]));
    }

    float m0 = -1e30f, m1 = -1e30f, l0 = 0.f, l1 = 0.f;
    float oacc[8][4];
    #pragma unroll
    for (int nt = 0; nt < 8; nt++)
        #pragma unroll
        for (int r = 0; r < 4; r++) oacc[nt][r] = 0.f;

    for (int kt = 0; kt <= qt; kt++) {
        __syncthreads();
        const float* Kt = Kg + (size_t)kt * 64 * 64;
        const float* Vt = Vg + (size_t)kt * 64 * 64;
        for (int i = tid; i < 64 * 16; i += 128) {
            int r = i >> 4, c4 = (i & 15) << 2;
            float4 kv = *(const float4*)&Kt[r * 64 + c4];
            float4 vv = *(const float4*)&Vt[r * 64 + c4];
            kv.x = tf32r(kv.x); kv.y = tf32r(kv.y);
            kv.z = tf32r(kv.z); kv.w = tf32r(kv.w);
            vv.x = tf32r(vv.x); vv.y = tf32r(vv.y);
            vv.z = tf32r(vv.z); vv.w = tf32r(vv.w);
            *(float4*)&Ks[r * AST + c4] = kv;
            *(float4*)&Vs[r * VST + c4] = vv;
        }
        __syncthreads();

        float sacc[8][4];
        #pragma unroll
        for (int nt = 0; nt < 8; nt++)
            #pragma unroll
            for (int r = 0; r < 4; r++) sacc[nt][r] = 0.f;
        #pragma unroll
        for (int ks = 0; ks < 8; ks++) {
            #pragma unroll
            for (int nt = 0; nt < 8; nt++) {
                uint32_t bf[2];
                bf[0] = __float_as_uint(Ks[(nt*8+gl) * AST + ks*8 + cl    ]);
                bf[1] = __float_as_uint(Ks[(nt*8+gl) * AST + ks*8 + cl + 4]);
                mma8(sacc[nt], qf[ks], bf);
            }
        }
        #pragma unroll
        for (int nt = 0; nt < 8; nt++)
            #pragma unroll
            for (int r = 0; r < 4; r++) sacc[nt][r] *= 0.125f;
        if (kt == qt) {
            #pragma unroll
            for (int nt = 0; nt < 8; nt++)
                #pragma unroll
                for (int j = 0; j < 2; j++) {
                    int key = nt * 8 + 2 * cl + j;
                    if (key > w * 16 + gl)     sacc[nt][j]     = 1e-9f;
                    if (key > w * 16 + gl + 8) sacc[nt][2 + j] = 1e-9f;
                }
        }
        float rm0 = -1e30f, rm1 = -1e30f;
        #pragma unroll
        for (int nt = 0; nt < 8; nt++) {
            rm0 = fmaxf(rm0, fmaxf(sacc[nt][0], sacc[nt][1]));
            rm1 = fmaxf(rm1, fmaxf(sacc[nt][2], sacc[nt][3]));
        }
        rm0 = fmaxf(rm0, __shfl_xor_sync(0xffffffffu, rm0, 1));
        rm0 = fmaxf(rm0, __shfl_xor_sync(0xffffffffu, rm0, 2));
        rm1 = fmaxf(rm1, __shfl_xor_sync(0xffffffffu, rm1, 1));
        rm1 = fmaxf(rm1, __shfl_xor_sync(0xffffffffu, rm1, 2));
        float mn0 = fmaxf(m0, rm0), mn1 = fmaxf(m1, rm1);
        float a0 = __expf(m0 - mn0), a1 = __expf(m1 - mn1);
        m0 = mn0; m1 = mn1;
        float rs0 = 0.f, rs1 = 0.f;
        #pragma unroll
        for (int nt = 0; nt < 8; nt++) {
            float p0 = __expf(sacc[nt][0] - mn0);
            float p1 = __expf(sacc[nt][1] - mn0);
            float p2 = __expf(sacc[nt][2] - mn1);
            float p3 = __expf(sacc[nt][3] - mn1);
            rs0 += p0 + p1; rs1 += p2 + p3;
            *(float2*)&Ps[(w*16+gl  ) * AST + nt*8 + 2*cl] =
                make_float2(tf32r(p0), tf32r(p1));
            *(float2*)&Ps[(w*16+gl+8) * AST + nt*8 + 2*cl] =
                make_float2(tf32r(p2), tf32r(p3));
        }
        rs0 += __shfl_xor_sync(0xffffffffu, rs0, 1);
        rs0 += __shfl_xor_sync(0xffffffffu, rs0, 2);
        rs1 += __shfl_xor_sync(0xffffffffu, rs1, 1);
        rs1 += __shfl_xor_sync(0xffffffffu, rs1, 2);
        l0 = l0 * a0 + rs0;
        l1 = l1 * a1 + rs1;
        #pragma unroll
        for (int nt = 0; nt < 8; nt++) {
            oacc[nt][0] *= a0; oacc[nt][1] *= a0;
            oacc[nt][2] *= a1; oacc[nt][3] *= a1;
        }
        __syncwarp();

        #pragma unroll
        for (int ks = 0; ks < 8; ks++) {
            uint32_t af[4];
            af[0] = __float_as_uint(Ps[(w*16+gl  ) * AST + ks*8 + cl    ]);
            af[1] = __float_as_uint(Ps[(w*16+gl+8) * AST + ks*8 + cl    ]);
            af[2] = __float_as_uint(Ps[(w*16+gl  ) * AST + ks*8 + cl + 4]);
            af[3] = __float_as_uint(Ps[(w*16+gl+8) * AST + ks*8 + cl + 4]);
            #pragma unroll
            for (int nt = 0; nt < 8; nt++) {
                uint32_t bf[2];
                bf[0] = __float_as_uint(Vs[(ks*8+cl  ) * VST + nt*8 + gl]);
                bf[1] = __float_as_uint(Vs[(ks*8+cl+4) * VST + nt*8 + gl]);
                mma8(oacc[nt], af, bf);
            }
        }
    }
    __syncthreads();

    // ---- virtual masked tile ----
    if (qt < 15) {
        const int mstart = (qt + 1) * 64;
        const float nmask = (float)(TT - mstart);
        {
            float ps = 0.f;
            const int col = tid & 63, seg = tid >> 6;
            for (int r = mstart + seg; r < TT; r += 2)
                ps += Vg[(size_t)r * 64 + col];
            Ps[seg * 64 + col] = ps;
        }
        __syncthreads();
        float nn0 = fmaxf(m0, 1e-9f), nn1 = fmaxf(m1, 1e-9f);
        float a0 = __expf(m0 - nn0), a1 = __expf(m1 - nn1);
        float e0 = __expf(1e-9f - nn0), e1 = __expf(1e-9f - nn1);
        l0 = l0 * a0 + nmask * e0;
        l1 = l1 * a1 + nmask * e1;
        #pragma unroll
        for (int nt = 0; nt < 8; nt++) {
            int col = nt * 8 + 2 * cl;
            float vs0 = Ps[col]     + Ps[64 + col];
            float vs1 = Ps[col + 1] + Ps[64 + col + 1];
            oacc[nt][0] = oacc[nt][0] * a0 + e0 * vs0;
            oacc[nt][1] = oacc[nt][1] * a0 + e0 * vs1;
            oacc[nt][2] = oacc[nt][2] * a1 + e1 * vs0;
            oacc[nt][3] = oacc[nt][3] * a1 + e1 * vs1;
        }
    }

    // ---- epilogue: x1 = x + y ----
    const float inv0 = 1.0f / l0, inv1 = 1.0f / l1;
    const size_t base0 = ((size_t)(b * TT + qg0 + w*16 + gl    )) * HH + head * HDIM;
    const size_t base1 = ((size_t)(b * TT + qg0 + w*16 + gl + 8)) * HH + head * HDIM;
    #pragma unroll
    for (int nt = 0; nt < 8; nt++) {
        int col = nt * 8 + 2 * cl;
        float2 xa = *(const float2*)&x[base0 + col];
        float2 xb = *(const float2*)&x[base1 + col];
        *(float2*)&x1[base0 + col] =
            make_float2(xa.x + oacc[nt][0] * inv0, xa.y + oacc[nt][1] * inv0);
        *(float2*)&x1[base1 + col] =
            make_float2(xb.x + oacc[nt][2] * inv1, xb.y + oacc[nt][3] * inv1);
    }
}

// ---------------- launch ----------------
extern "C" void kernel_launch(void* const* d_in, const int* in_sizes, int n_in,
                              void* d_out, int out_size)
{
    (void)in_sizes; (void)n_in; (void)out_size;
    const float* x    = (const float*)d_in[0];
    const float* ln1g = (const float*)d_in[1];
    const float* ln1b = (const float*)d_in[2];
    const float* ln2g = (const float*)d_in[3];
    const float* ln2b = (const float*)d_in[4];
    const float* Wq   = (const float*)d_in[5];
    const float* bq   = (const float*)d_in[6];
    const float* Wk   = (const float*)d_in[7];
    const float* bk   = (const float*)d_in[8];
    const float* Wv   = (const float*)d_in[9];
    const float* bv   = (const float*)d_in[10];
    const float* W1   = (const float*)d_in[11];
    const float* b1   = (const float*)d_in[12];
    const float* W2   = (const float*)d_in[13];
    const float* b2   = (const float*)d_in[14];
    float* out = (float*)d_out;

    float *hp, *q, *k, *v, *x1, *m1, *wqkv, *w1, *w2;
    cudaGetSymbolAddress((void**)&hp,   g_hp);
    cudaGetSymbolAddress((void**)&q,    g_q);
    cudaGetSymbolAddress((void**)&k,    g_k);
    cudaGetSymbolAddress((void**)&v,    g_v);
    cudaGetSymbolAddress((void**)&x1,   g_x1);
    cudaGetSymbolAddress((void**)&m1,   g_m1);
    cudaGetSymbolAddress((void**)&wqkv, g_wqkv);
    cudaGetSymbolAddress((void**)&w1,   g_w1);
    cudaGetSymbolAddress((void**)&w2,   g_w2);

    cudaFuncSetAttribute(attn_tc,
                         cudaFuncAttributeMaxDynamicSharedMemorySize, (int)ATTN_SMEM);
    cudaFuncSetAttribute(gemm_mma<EPI_QKV>,
                         cudaFuncAttributeMaxDynamicSharedMemorySize, GEMM_SMEM);
    cudaFuncSetAttribute(gemm_mma<EPI_GELU>,
                         cudaFuncAttributeMaxDynamicSharedMemorySize, GEMM_SMEM);
    cudaFuncSetAttribute(gemm_mma<EPI_RES>,
                         cudaFuncAttributeMaxDynamicSharedMemorySize, GEMM_SMEM);

    // fused weight prep (all 5 weights, one launch)
    prep_all<<<2816, 256>>>(Wq, Wk, Wv, W1, W2, wqkv, w1, w2);

    // LN1 -> hp (A-fragment order)
    ln_kernel<<<ROWS, 256>>>(x, ln1g, ln1b, hp);
    // fused QKV projection: N=3072, head-permuted stores into q/k/v
    gemm_mma<EPI_QKV><<<dim3(3 * HH / 128, ROWS / 256), 256, GEMM_SMEM>>>(
        hp, wqkv, bq, bk, bv, nullptr, q, k, v, 3 * HH, HH);
    // tensor-core attention + residual
    attn_tc<<<dim3(TT / 64, NHEAD, BB), 128, ATTN_SMEM>>>(q, k, v, x, x1);
    // LN2 -> hp (A-fragment order)
    ln_kernel<<<ROWS, 256>>>(x1, ln2g, ln2b, hp);
    // MLP: W1 gemm writes m1 in A-fragment order; W2 gemm reads it back
    gemm_mma<EPI_GELU><<<dim3(4 * HH / 128, ROWS / 256), 256, GEMM_SMEM>>>(
        hp, w1, b1, nullptr, nullptr, nullptr, m1, nullptr, nullptr, 4 * HH, HH);
    gemm_mma<EPI_RES><<<dim3(HH / 128, ROWS / 256), 256, GEMM_SMEM>>>(
        m1, w2, b2, nullptr, nullptr, x1, out, nullptr, nullptr, HH, 4 * HH);
}

// round 16
// speedup vs baseline: 1.0721x; 1.0721x over previous
#include <cuda_runtime.h>
#include <math.h>
#include <stdint.h>

// Problem constants
#define BB 4
#define TT 1024
#define HH 1024
#define NHEAD 16
#define HDIM 64
#define ROWS (BB*TT)          // 4096

// ---------------- scratch (no allocs allowed) ----------------
__device__ float g_hp  [ROWS*HH];       // LN out, A-fragment-order (KC=32)
__device__ float g_q   [ROWS*HH];       // [b][head][t][d], tf32-rounded
__device__ float g_k   [ROWS*HH];
__device__ float g_v   [ROWS*HH];
__device__ float g_x1  [ROWS*HH];       // x + attn out (row-major)
__device__ float g_m1  [ROWS*4*HH];     // gelu out, A-fragment-order (KC=128)
__device__ float g_wqkv[3*HH*HH];       // Wq|Wk|Wv, B-fragment-order, N=3072
__device__ float g_w1  [HH*4*HH];
__device__ float g_w2  [4*HH*HH];

// ---------------- helpers ----------------
__device__ __forceinline__ float tf32r(float x) {
    uint32_t r;
    asm("cvt.rna.tf32.f32 %0, %1;" : "=r"(r) : "f"(x));
    return __uint_as_float(r);
}
__device__ __forceinline__ uint32_t smem_u32(const void* p) {
    uint32_t a;
    asm("{ .reg .u64 t; cvta.to.shared.u64 t, %1; cvt.u32.u64 %0, t; }"
        : "=r"(a) : "l"(p));
    return a;
}
__device__ __forceinline__ void mma8(float* d, const uint32_t* a, const uint32_t* b) {
    asm volatile(
        "mma.sync.aligned.m16n8k8.row.col.f32.tf32.tf32.f32 "
        "{%0,%1,%2,%3}, {%4,%5,%6,%7}, {%8,%9}, {%0,%1,%2,%3};"
        : "+f"(d[0]), "+f"(d[1]), "+f"(d[2]), "+f"(d[3])
        : "r"(a[0]), "r"(a[1]), "r"(a[2]), "r"(a[3]), "r"(b[0]), "r"(b[1]));
}
#define CP16(dst, src) \
    asm volatile("cp.async.cg.shared.global [%0], [%1], 16;" :: "r"(dst), "l"(src))
#define CP_COMMIT() asm volatile("cp.async.commit_group;")
#define CP_WAIT1()  asm volatile("cp.async.wait_group 1;")

// ============ fused weight prep: all 5 weights -> B-fragment-order + tf32 ============
__global__ __launch_bounds__(256) void prep_all(
    const float* __restrict__ Wq, const float* __restrict__ Wk,
    const float* __restrict__ Wv, const float* __restrict__ W1,
    const float* __restrict__ W2,
    float* __restrict__ wqkv, float* __restrict__ w1, float* __restrict__ w2)
{
    __shared__ float s[32 * 132];
    const int t = threadIdx.x, blk = blockIdx.x;
    const float* W; float* out; int N, kc, nb;
    if (blk < 768) {
        int w = blk >> 8, r = blk & 255;
        nb = r >> 5; kc = r & 31; N = HH;
        W = (w == 0) ? Wq : (w == 1) ? Wk : Wv;
        out = wqkv + ((size_t)(w * 8 + nb) * 32 + kc) * 4096;
    } else if (blk < 1792) {
        int r = blk - 768;
        nb = r >> 5; kc = r & 31; N = 4 * HH;
        W = W1; out = w1 + ((size_t)nb * 32 + kc) * 4096;
    } else {
        int r = blk - 1792;
        nb = r >> 7; kc = r & 127; N = HH;
        W = W2; out = w2 + ((size_t)nb * 128 + kc) * 4096;
    }
    const float* Wg = W + (size_t)(kc * 32) * N + nb * 128;
    #pragma unroll
    for (int i = 0; i < 4; i++) {
        int fl = t + i * 256;
        int r = fl >> 5, c4 = (fl & 31) << 2;
        float4 v = *(const float4*)(Wg + (size_t)r * N + c4);
        s[r * 132 + c4 + 0] = v.x; s[r * 132 + c4 + 1] = v.y;
        s[r * 132 + c4 + 2] = v.z; s[r * 132 + c4 + 3] = v.w;
    }
    __syncthreads();
    float* o = out + t * 16;
    #pragma unroll
    for (int j4 = 0; j4 < 4; j4++) {
        float4 v; float* vp = (float*)&v;
        #pragma unroll
        for (int e = 0; e < 4; e++) {
            int f = t * 16 + j4 * 4 + e;
            int nt = f >> 8, ks = (f >> 6) & 3, ln = (f >> 1) & 31, rg = f & 1;
            int k3 = rg * 4 + (ln & 3);
            int nl = nt * 8 + ((ln >> 4) << 2) + ((ln >> 2) & 3);
            vp[e] = tf32r(s[(ks * 8 + k3) * 132 + nl]);
        }
        *(float4*)(o + j4 * 4) = v;
    }
}

// ---------------- LayerNorm -> A-fragment-order output (KC=32) ----------------
__global__ __launch_bounds__(256) void ln_kernel(
    const float* __restrict__ x, const float* __restrict__ g,
    const float* __restrict__ b, float* __restrict__ out)
{
    __shared__ float red[8];
    const int row = blockIdx.x, tid = threadIdx.x;
    const float* xr = x + (size_t)row * HH;
    float4 v = *(const float4*)(xr + tid * 4);

    float s = v.x + v.y + v.z + v.w;
    #pragma unroll
    for (int o = 16; o > 0; o >>= 1) s += __shfl_xor_sync(0xffffffffu, s, o);
    if ((tid & 31) == 0) red[tid >> 5] = s;
    __syncthreads();
    float tot = red[0]+red[1]+red[2]+red[3]+red[4]+red[5]+red[6]+red[7];
    const float mu = tot * (1.0f / HH);

    float dx = v.x - mu, dy = v.y - mu, dz = v.z - mu, dw = v.w - mu;
    float ss = dx*dx + dy*dy + dz*dz + dw*dw;
    #pragma unroll
    for (int o = 16; o > 0; o >>= 1) ss += __shfl_xor_sync(0xffffffffu, ss, o);
    __syncthreads();
    if ((tid & 31) == 0) red[tid >> 5] = ss;
    __syncthreads();
    float tot2 = red[0]+red[1]+red[2]+red[3]+red[4]+red[5]+red[6]+red[7];
    const float rs = rsqrtf(tot2 * (1.0f / HH) + 1e-5f);

    float4 gv = *(const float4*)(g + tid * 4);
    float4 bv = *(const float4*)(b + tid * 4);
    float o0 = dx * rs * gv.x + bv.x;
    float o1 = dy * rs * gv.y + bv.y;
    float o2 = dz * rs * gv.z + bv.z;
    float o3 = dw * rs * gv.w + bv.w;

    const int mb = row >> 7, mt = (row >> 4) & 7, hi = (row >> 3) & 1, gg = row & 7;
    const int kc = tid >> 3, ks = (tid >> 1) & 3, chi = tid & 1;
    float* op = out + ((size_t)(mb * 32 + kc)) * 4096
              + (mt * 4 + ks) * 128 + gg * 16 + hi + 2 * chi;
    op[0]  = tf32r(o0);
    op[4]  = tf32r(o1);
    op[8]  = tf32r(o2);
    op[12] = tf32r(o3);
}

// ============ tf32 mma.sync GEMM: 128x128 CTA, 4 warps of 64x64, 3-stage ============
// (reverted to the R14-validated 2-CTA/SM config)
enum { EPI_QKV = 0, EPI_GELU = 1, EPI_RES = 2 };

#define GEMM_SMEM (3 * 8192 * 4)   // 96 KB

template <int EPI>
__global__ __launch_bounds__(128, 2) void gemm_mma(
    const float* __restrict__ Ap, const float* __restrict__ Bp,
    const float* __restrict__ bias, const float* __restrict__ bias2,
    const float* __restrict__ bias3, const float* __restrict__ resid,
    float* __restrict__ C, float* __restrict__ C2, float* __restrict__ C3,
    int N, int Kd)
{
    extern __shared__ __align__(16) float smem[];   // [3][8192]
    const int tid = threadIdx.x, lane = tid & 31, wid = tid >> 5;
    const int wm = wid & 1, wn = wid >> 1;          // 2 x 2 warp grid, 64x64 tiles
    const int gl = lane >> 2, cl = lane & 3;
    const int bn = blockIdx.x * 128, bm = blockIdx.y * 128;
    const int KC = Kd >> 5;
    const float* Ach = Ap + (size_t)blockIdx.y * KC * 4096;
    const float* Bch = Bp + (size_t)blockIdx.x * KC * 4096;
    const uint32_t sb = smem_u32(smem);

    float acc[4][8][4];
    #pragma unroll
    for (int mi = 0; mi < 4; mi++)
        #pragma unroll
        for (int ni = 0; ni < 8; ni++)
            #pragma unroll
            for (int r = 0; r < 4; r++) acc[mi][ni][r] = 0.f;

    auto issue = [&](int st, int kc) {
        if (kc < KC) {
            const float* As = Ach + (size_t)kc * 4096;
            const float* Bs = Bch + (size_t)kc * 4096;
            uint32_t da = sb + st * 32768;
            uint32_t db = da + 16384;
            #pragma unroll
            for (int i = 0; i < 8; i++) {
                int fl = (tid + i * 128) * 4;
                CP16(da + fl * 4, As + fl);
                CP16(db + fl * 4, Bs + fl);
            }
        }
        CP_COMMIT();
    };

    issue(0, 0);
    issue(1, 1);
    for (int kc = 0; kc < KC; kc++) {
        CP_WAIT1();
        __syncthreads();
        issue((kc + 2) % 3, kc + 2);
        const float* sA = smem + (kc % 3) * 8192;
        const float* sB = sA + 4096;
        #pragma unroll
        for (int ks = 0; ks < 4; ks++) {
            uint32_t af[4][4];
            uint32_t bf[8][2];
            #pragma unroll
            for (int mi = 0; mi < 4; mi++) {
                int mt = wm * 4 + mi;
                *(uint4*)af[mi] =
                    *(const uint4*)&sA[((mt << 2) + ks) * 128 + (lane << 2)];
            }
            #pragma unroll
            for (int ni = 0; ni < 8; ni++) {
                int nt = wn * 8 + ni;
                *(uint2*)bf[ni] =
                    *(const uint2*)&sB[((nt << 2) + ks) * 64 + (lane << 1)];
            }
            #pragma unroll
            for (int mi = 0; mi < 4; mi++)
                #pragma unroll
                for (int ni = 0; ni < 8; ni++)
                    mma8(acc[mi][ni], af[mi], bf[ni]);
        }
    }

    // ---- epilogue ----
    const float* bs = bias;
    float* Cd = C;
    int bnl = bn;
    if (EPI == EPI_QKV) {
        const int which = bn >> 10;
        bs  = (which == 0) ? bias : (which == 1) ? bias2 : bias3;
        Cd  = (which == 0) ? C    : (which == 1) ? C2    : C3;
        bnl = bn & 1023;
    }
    #pragma unroll
    for (int mi = 0; mi < 4; mi++) {
        const int r0 = bm + wm * 64 + mi * 16 + gl;
        #pragma unroll
        for (int ni = 0; ni < 8; ni++) {
            const int colw = wn * 64 + ni * 8 + (cl << 1);
            const int col = (EPI == EPI_QKV) ? (bnl + colw) : (bn + colw);
            const float bx = __ldg(&bs[col]);
            const float by = __ldg(&bs[col + 1]);
            float v00 = acc[mi][ni][0] + bx, v01 = acc[mi][ni][1] + by;
            float v10 = acc[mi][ni][2] + bx, v11 = acc[mi][ni][3] + by;
            if (EPI == EPI_QKV) {
                // store q/k/v pre-rounded to tf32 (attention drops its cvts)
                const int head = col >> 6, d0 = col & 63;
                #pragma unroll
                for (int hh2 = 0; hh2 < 2; hh2++) {
                    const int row = r0 + hh2 * 8;
                    float* Cp = Cd + ((size_t)((row >> 10) * NHEAD + head)) * (TT * HDIM)
                                   + (size_t)(row & (TT - 1)) * HDIM + d0;
                    float2 o = hh2 ? make_float2(tf32r(v10), tf32r(v11))
                                   : make_float2(tf32r(v00), tf32r(v01));
                    *(float2*)Cp = o;
                }
            } else if (EPI == EPI_GELU) {
                float t00 = 0.5f * v00 * (1.0f + erff(v00 * 0.70710678118654752f));
                float t01 = 0.5f * v01 * (1.0f + erff(v01 * 0.70710678118654752f));
                float t10 = 0.5f * v10 * (1.0f + erff(v10 * 0.70710678118654752f));
                float t11 = 0.5f * v11 * (1.0f + erff(v11 * 0.70710678118654752f));
                size_t idx = ((size_t)((r0 >> 7) * 128 + (col >> 5))) * 4096
                           + ((((r0 >> 4) & 7) << 2) + ((col >> 3) & 3)) * 128
                           + (((r0 & 7) << 2) + (col & 3)) * 4
                           + ((col >> 2) & 1) * 2;
                *(float2*)(Cd + idx)     = make_float2(tf32r(t00), tf32r(t10));
                *(float2*)(Cd + idx + 4) = make_float2(tf32r(t01), tf32r(t11));
            } else {
                float2 ra = *(const float2*)(resid + (size_t)r0 * N + col);
                float2 rb = *(const float2*)(resid + (size_t)(r0 + 8) * N + col);
                *(float2*)(Cd + (size_t)r0 * N + col) =
                    make_float2(v00 + ra.x, v01 + ra.y);
                *(float2*)(Cd + (size_t)(r0 + 8) * N + col) =
                    make_float2(v10 + rb.x, v11 + rb.y);
            }
        }
    }
}

// ======== Tensor-core attention: Q-tile 128, 8 warps x 16 q-rows ========
// K/V tile loads amortized over 2x q-rows (0.53x tile-load work vs Q-tile 64).
// q/k/v arrive pre-rounded to tf32 (QKV epilogue) -> no cvt in load loop.
#define AST 68
#define VST 72
#define ATTN_SMEM (size_t)((64*AST + 64*VST + 128*AST) * sizeof(float))

__global__ __launch_bounds__(256, 2) void attn_tc(
    const float* __restrict__ q, const float* __restrict__ k,
    const float* __restrict__ v, const float* __restrict__ x,
    float* __restrict__ x1)
{
    extern __shared__ __align__(16) float sm[];
    float* Ks = sm;                 // 64 x AST
    float* Vs = Ks + 64 * AST;      // 64 x VST
    float* Ps = Vs + 64 * VST;      // 128 x AST (Q staging, then P, then vsum)

    const int tid = threadIdx.x, lane = tid & 31, w = tid >> 5;  // w: 0..7
    const int gl = lane >> 2, cl = lane & 3;
    const int qtb = (int)gridDim.x - 1 - (int)blockIdx.x;        // heavy first
    const int head = blockIdx.y, b = blockIdx.z;
    const int qg0 = qtb * 128;
    const int qrow0 = qg0 + w * 16 + gl, qrow1 = qrow0 + 8;

    const float* Qg = q + (size_t)((b * NHEAD + head) * TT + qg0) * HDIM;
    const float* Kg = k + (size_t)(b * NHEAD + head) * TT * HDIM;
    const float* Vg = v + (size_t)(b * NHEAD + head) * TT * HDIM;

    // stage Q (128x64) into Ps, pull this warp's A-fragments
    for (int i = tid; i < 128 * 16; i += 256) {
        int r = i >> 4, c4 = (i & 15) << 2;
        *(float4*)&Ps[r * AST + c4] = *(const float4*)&Qg[r * 64 + c4];
    }
    __syncthreads();
    uint32_t qf[8][4];
    #pragma unroll
    for (int ks = 0; ks < 8; ks++) {
        qf[ks][0] = __float_as_uint(Ps[(w*16+gl  ) * AST + ks*8 + cl    ]);
        qf[ks][1] = __float_as_uint(Ps[(w*16+gl+8) * AST + ks*8 + cl    ]);
        qf[ks][2] = __float_as_uint(Ps[(w*16+gl  ) * AST + ks*8 + cl + 4]);
        qf[ks][3] = __float_as_uint(Ps[(w*16+gl+8) * AST + ks*8 + cl + 4]);
    }
    // no extra sync needed: P writes later touch only this warp's own rows

    float m0 = -1e30f, m1 = -1e30f, l0 = 0.f, l1 = 0.f;
    float oacc[8][4];
    #pragma unroll
    for (int nt = 0; nt < 8; nt++)
        #pragma unroll
        for (int r = 0; r < 4; r++) oacc[nt][r] = 0.f;

    const int ktmax = 2 * qtb + 1;        // covers keys <= qg0+127
    for (int kt = 0; kt <= ktmax; kt++) {
        __syncthreads();
        const float* Kt = Kg + (size_t)kt * 64 * 64;
        const float* Vt = Vg + (size_t)kt * 64 * 64;
        for (int i = tid; i < 64 * 16; i += 256) {
            int r = i >> 4, c4 = (i & 15) << 2;
            *(float4*)&Ks[r * AST + c4] = *(const float4*)&Kt[r * 64 + c4];
            *(float4*)&Vs[r * VST + c4] = *(const float4*)&Vt[r * 64 + c4];
        }
        __syncthreads();

        const int kp0 = kt * 64;
        float sacc[8][4];
        #pragma unroll
        for (int nt = 0; nt < 8; nt++)
            #pragma unroll
            for (int r = 0; r < 4; r++) sacc[nt][r] = 0.f;
        #pragma unroll
        for (int ks = 0; ks < 8; ks++) {
            #pragma unroll
            for (int nt = 0; nt < 8; nt++) {
                uint32_t bf[2];
                bf[0] = __float_as_uint(Ks[(nt*8+gl) * AST + ks*8 + cl    ]);
                bf[1] = __float_as_uint(Ks[(nt*8+gl) * AST + ks*8 + cl + 4]);
                mma8(sacc[nt], qf[ks], bf);
            }
        }
        #pragma unroll
        for (int nt = 0; nt < 8; nt++)
            #pragma unroll
            for (int r = 0; r < 4; r++) sacc[nt][r] *= 0.125f;
        if (kp0 + 63 > qg0 + w * 16) {    // this warp's rows touch the mask
            #pragma unroll
            for (int nt = 0; nt < 8; nt++)
                #pragma unroll
                for (int j = 0; j < 2; j++) {
                    int key = kp0 + nt * 8 + 2 * cl + j;
                    if (key > qrow0) sacc[nt][j]     = 1e-9f;
                    if (key > qrow1) sacc[nt][2 + j] = 1e-9f;
                }
        }
        float rm0 = -1e30f, rm1 = -1e30f;
        #pragma unroll
        for (int nt = 0; nt < 8; nt++) {
            rm0 = fmaxf(rm0, fmaxf(sacc[nt][0], sacc[nt][1]));
            rm1 = fmaxf(rm1, fmaxf(sacc[nt][2], sacc[nt][3]));
        }
        rm0 = fmaxf(rm0, __shfl_xor_sync(0xffffffffu, rm0, 1));
        rm0 = fmaxf(rm0, __shfl_xor_sync(0xffffffffu, rm0, 2));
        rm1 = fmaxf(rm1, __shfl_xor_sync(0xffffffffu, rm1, 1));
        rm1 = fmaxf(rm1, __shfl_xor_sync(0xffffffffu, rm1, 2));
        float mn0 = fmaxf(m0, rm0), mn1 = fmaxf(m1, rm1);
        float a0 = __expf(m0 - mn0), a1 = __expf(m1 - mn1);
        m0 = mn0; m1 = mn1;
        float rs0 = 0.f, rs1 = 0.f;
        #pragma unroll
        for (int nt = 0; nt < 8; nt++) {
            float p0 = __expf(sacc[nt][0] - mn0);
            float p1 = __expf(sacc[nt][1] - mn0);
            float p2 = __expf(sacc[nt][2] - mn1);
            float p3 = __expf(sacc[nt][3] - mn1);
            rs0 += p0 + p1; rs1 += p2 + p3;
            *(float2*)&Ps[(w*16+gl  ) * AST + nt*8 + 2*cl] =
                make_float2(tf32r(p0), tf32r(p1));
            *(float2*)&Ps[(w*16+gl+8) * AST + nt*8 + 2*cl] =
                make_float2(tf32r(p2), tf32r(p3));
        }
        rs0 += __shfl_xor_sync(0xffffffffu, rs0, 1);
        rs0 += __shfl_xor_sync(0xffffffffu, rs0, 2);
        rs1 += __shfl_xor_sync(0xffffffffu, rs1, 1);
        rs1 += __shfl_xor_sync(0xffffffffu, rs1, 2);
        l0 = l0 * a0 + rs0;
        l1 = l1 * a1 + rs1;
        #pragma unroll
        for (int nt = 0; nt < 8; nt++) {
            oacc[nt][0] *= a0; oacc[nt][1] *= a0;
            oacc[nt][2] *= a1; oacc[nt][3] *= a1;
        }
        __syncwarp();   // P rows are warp-private

        #pragma unroll
        for (int ks = 0; ks < 8; ks++) {
            uint32_t af[4];
            af[0] = __float_as_uint(Ps[(w*16+gl  ) * AST + ks*8 + cl    ]);
            af[1] = __float_as_uint(Ps[(w*16+gl+8) * AST + ks*8 + cl    ]);
            af[2] = __float_as_uint(Ps[(w*16+gl  ) * AST + ks*8 + cl + 4]);
            af[3] = __float_as_uint(Ps[(w*16+gl+8) * AST + ks*8 + cl + 4]);
            #pragma unroll
            for (int nt = 0; nt < 8; nt++) {
                uint32_t bf[2];
                bf[0] = __float_as_uint(Vs[(ks*8+cl  ) * VST + nt*8 + gl]);
                bf[1] = __float_as_uint(Vs[(ks*8+cl+4) * VST + nt*8 + gl]);
                mma8(oacc[nt], af, bf);
            }
        }
    }
    __syncthreads();   // Ps free for vsum reuse

    // ---- virtual masked tile: rows [qg0+128, 1024) all score 1e-9 ----
    if (qtb < (int)gridDim.x - 1) {
        const int mstart = qg0 + 128;
        const float nmask = (float)(TT - mstart);
        {
            float ps = 0.f;
            const int col = tid & 63, seg = tid >> 6;   // 4 segments
            for (int r = mstart + seg; r < TT; r += 4)
                ps += Vg[(size_t)r * 64 + col];
            Ps[seg * 64 + col] = ps;
        }
        __syncthreads();
        float nn0 = fmaxf(m0, 1e-9f), nn1 = fmaxf(m1, 1e-9f);
        float a0 = __expf(m0 - nn0), a1 = __expf(m1 - nn1);
        float e0 = __expf(1e-9f - nn0), e1 = __expf(1e-9f - nn1);
        l0 = l0 * a0 + nmask * e0;
        l1 = l1 * a1 + nmask * e1;
        #pragma unroll
        for (int nt = 0; nt < 8; nt++) {
            int col = nt * 8 + 2 * cl;
            float vs0 = Ps[col]     + Ps[64+col]   + Ps[128+col]   + Ps[192+col];
            float vs1 = Ps[col + 1] + Ps[64+col+1] + Ps[128+col+1] + Ps[192+col+1];
            oacc[nt][0] = oacc[nt][0] * a0 + e0 * vs0;
            oacc[nt][1] = oacc[nt][1] * a0 + e0 * vs1;
            oacc[nt][2] = oacc[nt][2] * a1 + e1 * vs0;
            oacc[nt][3] = oacc[nt][3] * a1 + e1 * vs1;
        }
    }

    // ---- epilogue: x1 = x + y ----
    const float inv0 = 1.0f / l0, inv1 = 1.0f / l1;
    const size_t base0 = ((size_t)(b * TT + qrow0)) * HH + head * HDIM;
    const size_t base1 = ((size_t)(b * TT + qrow1)) * HH + head * HDIM;
    #pragma unroll
    for (int nt = 0; nt < 8; nt++) {
        int col = nt * 8 + 2 * cl;
        float2 xa = *(const float2*)&x[base0 + col];
        float2 xb = *(const float2*)&x[base1 + col];
        *(float2*)&x1[base0 + col] =
            make_float2(xa.x + oacc[nt][0] * inv0, xa.y + oacc[nt][1] * inv0);
        *(float2*)&x1[base1 + col] =
            make_float2(xb.x + oacc[nt][2] * inv1, xb.y + oacc[nt][3] * inv1);
    }
}

// ---------------- launch ----------------
extern "C" void kernel_launch(void* const* d_in, const int* in_sizes, int n_in,
                              void* d_out, int out_size)
{
    (void)in_sizes; (void)n_in; (void)out_size;
    const float* x    = (const float*)d_in[0];
    const float* ln1g = (const float*)d_in[1];
    const float* ln1b = (const float*)d_in[2];
    const float* ln2g = (const float*)d_in[3];
    const float* ln2b = (const float*)d_in[4];
    const float* Wq   = (const float*)d_in[5];
    const float* bq   = (const float*)d_in[6];
    const float* Wk   = (const float*)d_in[7];
    const float* bk   = (const float*)d_in[8];
    const float* Wv   = (const float*)d_in[9];
    const float* bv   = (const float*)d_in[10];
    const float* W1   = (const float*)d_in[11];
    const float* b1   = (const float*)d_in[12];
    const float* W2   = (const float*)d_in[13];
    const float* b2   = (const float*)d_in[14];
    float* out = (float*)d_out;

    float *hp, *q, *k, *v, *x1, *m1, *wqkv, *w1, *w2;
    cudaGetSymbolAddress((void**)&hp,   g_hp);
    cudaGetSymbolAddress((void**)&q,    g_q);
    cudaGetSymbolAddress((void**)&k,    g_k);
    cudaGetSymbolAddress((void**)&v,    g_v);
    cudaGetSymbolAddress((void**)&x1,   g_x1);
    cudaGetSymbolAddress((void**)&m1,   g_m1);
    cudaGetSymbolAddress((void**)&wqkv, g_wqkv);
    cudaGetSymbolAddress((void**)&w1,   g_w1);
    cudaGetSymbolAddress((void**)&w2,   g_w2);

    cudaFuncSetAttribute(attn_tc,
                         cudaFuncAttributeMaxDynamicSharedMemorySize, (int)ATTN_SMEM);
    cudaFuncSetAttribute(gemm_mma<EPI_QKV>,
                         cudaFuncAttributeMaxDynamicSharedMemorySize, GEMM_SMEM);
    cudaFuncSetAttribute(gemm_mma<EPI_GELU>,
                         cudaFuncAttributeMaxDynamicSharedMemorySize, GEMM_SMEM);
    cudaFuncSetAttribute(gemm_mma<EPI_RES>,
                         cudaFuncAttributeMaxDynamicSharedMemorySize, GEMM_SMEM);

    // fused weight prep (all 5 weights, one launch)
    prep_all<<<2816, 256>>>(Wq, Wk, Wv, W1, W2, wqkv, w1, w2);

    // LN1 -> hp (A-fragment order)
    ln_kernel<<<ROWS, 256>>>(x, ln1g, ln1b, hp);
    // fused QKV projection (tf32-rounded stores): N=3072
    gemm_mma<EPI_QKV><<<dim3(3 * HH / 128, ROWS / 128), 128, GEMM_SMEM>>>(
        hp, wqkv, bq, bk, bv, nullptr, q, k, v, 3 * HH, HH);
    // tensor-core attention (Q-tile 128) + residual
    attn_tc<<<dim3(TT / 128, NHEAD, BB), 256, ATTN_SMEM>>>(q, k, v, x, x1);
    // LN2 -> hp (A-fragment order)
    ln_kernel<<<ROWS, 256>>>(x1, ln2g, ln2b, hp);
    // MLP: W1 gemm writes m1 in A-fragment order; W2 gemm reads it back
    gemm_mma<EPI_GELU><<<dim3(4 * HH / 128, ROWS / 128), 128, GEMM_SMEM>>>(
        hp, w1, b1, nullptr, nullptr, nullptr, m1, nullptr, nullptr, 4 * HH, HH);
    gemm_mma<EPI_RES><<<dim3(HH / 128, ROWS / 128), 128, GEMM_SMEM>>>(
        m1, w2, b2, nullptr, nullptr, x1, out, nullptr, nullptr, HH, 4 * HH);
}

// round 17
// speedup vs baseline: 1.0878x; 1.0146x over previous
#include <cuda_runtime.h>
#include <math.h>
#include <stdint.h>

// Problem constants
#define BB 4
#define TT 1024
#define HH 1024
#define NHEAD 16
#define HDIM 64
#define ROWS (BB*TT)          // 4096

// ---------------- scratch (no allocs allowed) ----------------
__device__ float g_hp  [ROWS*HH];       // LN out, A-fragment-order (KC=32)
__device__ float g_q   [ROWS*HH];       // [b][head][t][d], tf32-rounded
__device__ float g_k   [ROWS*HH];
__device__ float g_v   [ROWS*HH];
__device__ float g_x1  [ROWS*HH];       // x + attn out (row-major)
__device__ float g_m1  [ROWS*4*HH];     // gelu out, A-fragment-order (KC=128)
__device__ float g_wqkv[3*HH*HH];       // Wq|Wk|Wv, B-fragment-order, N=3072
__device__ float g_w1  [HH*4*HH];
__device__ float g_w2  [4*HH*HH];

// ---------------- helpers ----------------
__device__ __forceinline__ float tf32r(float x) {
    uint32_t r;
    asm("cvt.rna.tf32.f32 %0, %1;" : "=r"(r) : "f"(x));
    return __uint_as_float(r);
}
__device__ __forceinline__ uint32_t smem_u32(const void* p) {
    uint32_t a;
    asm("{ .reg .u64 t; cvta.to.shared.u64 t, %1; cvt.u32.u64 %0, t; }"
        : "=r"(a) : "l"(p));
    return a;
}
__device__ __forceinline__ void mma8(float* d, const uint32_t* a, const uint32_t* b) {
    asm volatile(
        "mma.sync.aligned.m16n8k8.row.col.f32.tf32.tf32.f32 "
        "{%0,%1,%2,%3}, {%4,%5,%6,%7}, {%8,%9}, {%0,%1,%2,%3};"
        : "+f"(d[0]), "+f"(d[1]), "+f"(d[2]), "+f"(d[3])
        : "r"(a[0]), "r"(a[1]), "r"(a[2]), "r"(a[3]), "r"(b[0]), "r"(b[1]));
}
#define CP16(dst, src) \
    asm volatile("cp.async.cg.shared.global [%0], [%1], 16;" :: "r"(dst), "l"(src))
#define CP_COMMIT() asm volatile("cp.async.commit_group;")
#define CP_WAIT1()  asm volatile("cp.async.wait_group 1;")

// ============ fused weight prep: all 5 weights -> B-fragment-order + tf32 ============
__global__ __launch_bounds__(256) void prep_all(
    const float* __restrict__ Wq, const float* __restrict__ Wk,
    const float* __restrict__ Wv, const float* __restrict__ W1,
    const float* __restrict__ W2,
    float* __restrict__ wqkv, float* __restrict__ w1, float* __restrict__ w2)
{
    __shared__ float s[32 * 132];
    const int t = threadIdx.x, blk = blockIdx.x;
    const float* W; float* out; int N, kc, nb;
    if (blk < 768) {
        int w = blk >> 8, r = blk & 255;
        nb = r >> 5; kc = r & 31; N = HH;
        W = (w == 0) ? Wq : (w == 1) ? Wk : Wv;
        out = wqkv + ((size_t)(w * 8 + nb) * 32 + kc) * 4096;
    } else if (blk < 1792) {
        int r = blk - 768;
        nb = r >> 5; kc = r & 31; N = 4 * HH;
        W = W1; out = w1 + ((size_t)nb * 32 + kc) * 4096;
    } else {
        int r = blk - 1792;
        nb = r >> 7; kc = r & 127; N = HH;
        W = W2; out = w2 + ((size_t)nb * 128 + kc) * 4096;
    }
    const float* Wg = W + (size_t)(kc * 32) * N + nb * 128;
    #pragma unroll
    for (int i = 0; i < 4; i++) {
        int fl = t + i * 256;
        int r = fl >> 5, c4 = (fl & 31) << 2;
        float4 v = *(const float4*)(Wg + (size_t)r * N + c4);
        s[r * 132 + c4 + 0] = v.x; s[r * 132 + c4 + 1] = v.y;
        s[r * 132 + c4 + 2] = v.z; s[r * 132 + c4 + 3] = v.w;
    }
    __syncthreads();
    float* o = out + t * 16;
    #pragma unroll
    for (int j4 = 0; j4 < 4; j4++) {
        float4 v; float* vp = (float*)&v;
        #pragma unroll
        for (int e = 0; e < 4; e++) {
            int f = t * 16 + j4 * 4 + e;
            int nt = f >> 8, ks = (f >> 6) & 3, ln = (f >> 1) & 31, rg = f & 1;
            int k3 = rg * 4 + (ln & 3);
            int nl = nt * 8 + ((ln >> 4) << 2) + ((ln >> 2) & 3);
            vp[e] = tf32r(s[(ks * 8 + k3) * 132 + nl]);
        }
        *(float4*)(o + j4 * 4) = v;
    }
}

// ---------------- LayerNorm -> A-fragment-order output (KC=32) ----------------
__global__ __launch_bounds__(256) void ln_kernel(
    const float* __restrict__ x, const float* __restrict__ g,
    const float* __restrict__ b, float* __restrict__ out)
{
    __shared__ float red[8];
    const int row = blockIdx.x, tid = threadIdx.x;
    const float* xr = x + (size_t)row * HH;
    float4 v = *(const float4*)(xr + tid * 4);

    float s = v.x + v.y + v.z + v.w;
    #pragma unroll
    for (int o = 16; o > 0; o >>= 1) s += __shfl_xor_sync(0xffffffffu, s, o);
    if ((tid & 31) == 0) red[tid >> 5] = s;
    __syncthreads();
    float tot = red[0]+red[1]+red[2]+red[3]+red[4]+red[5]+red[6]+red[7];
    const float mu = tot * (1.0f / HH);

    float dx = v.x - mu, dy = v.y - mu, dz = v.z - mu, dw = v.w - mu;
    float ss = dx*dx + dy*dy + dz*dz + dw*dw;
    #pragma unroll
    for (int o = 16; o > 0; o >>= 1) ss += __shfl_xor_sync(0xffffffffu, ss, o);
    __syncthreads();
    if ((tid & 31) == 0) red[tid >> 5] = ss;
    __syncthreads();
    float tot2 = red[0]+red[1]+red[2]+red[3]+red[4]+red[5]+red[6]+red[7];
    const float rs = rsqrtf(tot2 * (1.0f / HH) + 1e-5f);

    float4 gv = *(const float4*)(g + tid * 4);
    float4 bv = *(const float4*)(b + tid * 4);
    float o0 = dx * rs * gv.x + bv.x;
    float o1 = dy * rs * gv.y + bv.y;
    float o2 = dz * rs * gv.z + bv.z;
    float o3 = dw * rs * gv.w + bv.w;

    const int mb = row >> 7, mt = (row >> 4) & 7, hi = (row >> 3) & 1, gg = row & 7;
    const int kc = tid >> 3, ks = (tid >> 1) & 3, chi = tid & 1;
    float* op = out + ((size_t)(mb * 32 + kc)) * 4096
              + (mt * 4 + ks) * 128 + gg * 16 + hi + 2 * chi;
    op[0]  = tf32r(o0);
    op[4]  = tf32r(o1);
    op[8]  = tf32r(o2);
    op[12] = tf32r(o3);
}

// ============ tf32 mma.sync GEMM: 128x128 CTA, 4 warps of 64x64, 3-stage ============
enum { EPI_QKV = 0, EPI_GELU = 1, EPI_RES = 2 };

#define GEMM_SMEM (3 * 8192 * 4)   // 96 KB

template <int EPI>
__global__ __launch_bounds__(128, 2) void gemm_mma(
    const float* __restrict__ Ap, const float* __restrict__ Bp,
    const float* __restrict__ bias, const float* __restrict__ bias2,
    const float* __restrict__ bias3, const float* __restrict__ resid,
    float* __restrict__ C, float* __restrict__ C2, float* __restrict__ C3,
    int N, int Kd)
{
    extern __shared__ __align__(16) float smem[];   // [3][8192]
    const int tid = threadIdx.x, lane = tid & 31, wid = tid >> 5;
    const int wm = wid & 1, wn = wid >> 1;          // 2 x 2 warp grid, 64x64 tiles
    const int gl = lane >> 2, cl = lane & 3;
    const int bn = blockIdx.x * 128, bm = blockIdx.y * 128;
    const int KC = Kd >> 5;
    const float* Ach = Ap + (size_t)blockIdx.y * KC * 4096;
    const float* Bch = Bp + (size_t)blockIdx.x * KC * 4096;
    const uint32_t sb = smem_u32(smem);

    float acc[4][8][4];
    #pragma unroll
    for (int mi = 0; mi < 4; mi++)
        #pragma unroll
        for (int ni = 0; ni < 8; ni++)
            #pragma unroll
            for (int r = 0; r < 4; r++) acc[mi][ni][r] = 0.f;

    auto issue = [&](int st, int kc) {
        if (kc < KC) {
            const float* As = Ach + (size_t)kc * 4096;
            const float* Bs = Bch + (size_t)kc * 4096;
            uint32_t da = sb + st * 32768;
            uint32_t db = da + 16384;
            #pragma unroll
            for (int i = 0; i < 8; i++) {
                int fl = (tid + i * 128) * 4;
                CP16(da + fl * 4, As + fl);
                CP16(db + fl * 4, Bs + fl);
            }
        }
        CP_COMMIT();
    };

    issue(0, 0);
    issue(1, 1);
    for (int kc = 0; kc < KC; kc++) {
        CP_WAIT1();
        __syncthreads();
        issue((kc + 2) % 3, kc + 2);
        const float* sA = smem + (kc % 3) * 8192;
        const float* sB = sA + 4096;
        #pragma unroll
        for (int ks = 0; ks < 4; ks++) {
            uint32_t af[4][4];
            uint32_t bf[8][2];
            #pragma unroll
            for (int mi = 0; mi < 4; mi++) {
                int mt = wm * 4 + mi;
                *(uint4*)af[mi] =
                    *(const uint4*)&sA[((mt << 2) + ks) * 128 + (lane << 2)];
            }
            #pragma unroll
            for (int ni = 0; ni < 8; ni++) {
                int nt = wn * 8 + ni;
                *(uint2*)bf[ni] =
                    *(const uint2*)&sB[((nt << 2) + ks) * 64 + (lane << 1)];
            }
            #pragma unroll
            for (int mi = 0; mi < 4; mi++)
                #pragma unroll
                for (int ni = 0; ni < 8; ni++)
                    mma8(acc[mi][ni], af[mi], bf[ni]);
        }
    }

    // ---- epilogue ----
    const float* bs = bias;
    float* Cd = C;
    int bnl = bn;
    if (EPI == EPI_QKV) {
        const int which = bn >> 10;
        bs  = (which == 0) ? bias : (which == 1) ? bias2 : bias3;
        Cd  = (which == 0) ? C    : (which == 1) ? C2    : C3;
        bnl = bn & 1023;
    }
    #pragma unroll
    for (int mi = 0; mi < 4; mi++) {
        const int r0 = bm + wm * 64 + mi * 16 + gl;
        #pragma unroll
        for (int ni = 0; ni < 8; ni++) {
            const int colw = wn * 64 + ni * 8 + (cl << 1);
            const int col = (EPI == EPI_QKV) ? (bnl + colw) : (bn + colw);
            const float bx = __ldg(&bs[col]);
            const float by = __ldg(&bs[col + 1]);
            float v00 = acc[mi][ni][0] + bx, v01 = acc[mi][ni][1] + by;
            float v10 = acc[mi][ni][2] + bx, v11 = acc[mi][ni][3] + by;
            if (EPI == EPI_QKV) {
                // store q/k/v pre-rounded to tf32 (attention drops its cvts)
                const int head = col >> 6, d0 = col & 63;
                #pragma unroll
                for (int hh2 = 0; hh2 < 2; hh2++) {
                    const int row = r0 + hh2 * 8;
                    float* Cp = Cd + ((size_t)((row >> 10) * NHEAD + head)) * (TT * HDIM)
                                   + (size_t)(row & (TT - 1)) * HDIM + d0;
                    float2 o = hh2 ? make_float2(tf32r(v10), tf32r(v11))
                                   : make_float2(tf32r(v00), tf32r(v01));
                    *(float2*)Cp = o;
                }
            } else if (EPI == EPI_GELU) {
                float t00 = 0.5f * v00 * (1.0f + erff(v00 * 0.70710678118654752f));
                float t01 = 0.5f * v01 * (1.0f + erff(v01 * 0.70710678118654752f));
                float t10 = 0.5f * v10 * (1.0f + erff(v10 * 0.70710678118654752f));
                float t11 = 0.5f * v11 * (1.0f + erff(v11 * 0.70710678118654752f));
                size_t idx = ((size_t)((r0 >> 7) * 128 + (col >> 5))) * 4096
                           + ((((r0 >> 4) & 7) << 2) + ((col >> 3) & 3)) * 128
                           + (((r0 & 7) << 2) + (col & 3)) * 4
                           + ((col >> 2) & 1) * 2;
                *(float2*)(Cd + idx)     = make_float2(tf32r(t00), tf32r(t10));
                *(float2*)(Cd + idx + 4) = make_float2(tf32r(t01), tf32r(t11));
            } else {
                float2 ra = *(const float2*)(resid + (size_t)r0 * N + col);
                float2 rb = *(const float2*)(resid + (size_t)(r0 + 8) * N + col);
                *(float2*)(Cd + (size_t)r0 * N + col) =
                    make_float2(v00 + ra.x, v01 + ra.y);
                *(float2*)(Cd + (size_t)(r0 + 8) * N + col) =
                    make_float2(v10 + rb.x, v11 + rb.y);
            }
        }
    }
}

// ======== Tensor-core attention: Q-tile 64, 4 warps x 16 q-rows (R14 config) ========
// q/k/v arrive pre-rounded to tf32 -> no cvt in load loop.
#define AST 68
#define VST 72
#define ATTN_SMEM (size_t)((64*AST + 64*VST + 64*AST) * sizeof(float))

__global__ __launch_bounds__(128, 3) void attn_tc(
    const float* __restrict__ q, const float* __restrict__ k,
    const float* __restrict__ v, const float* __restrict__ x,
    float* __restrict__ x1)
{
    extern __shared__ __align__(16) float sm[];
    float* Ks = sm;                 // 64 x AST (also Q staging)
    float* Vs = Ks + 64 * AST;      // 64 x VST
    float* Ps = Vs + 64 * VST;      // 64 x AST (P; vsum scratch after loop)

    const int tid = threadIdx.x, lane = tid & 31, w = tid >> 5;
    const int gl = lane >> 2, cl = lane & 3;
    const int qt = (int)gridDim.x - 1 - (int)blockIdx.x;   // heavy tiles first
    const int head = blockIdx.y, b = blockIdx.z;
    const int qg0 = qt * 64;

    const float* Qg = q + (size_t)((b * NHEAD + head) * TT + qg0) * HDIM;
    const float* Kg = k + (size_t)(b * NHEAD + head) * TT * HDIM;
    const float* Vg = v + (size_t)(b * NHEAD + head) * TT * HDIM;

    for (int i = tid; i < 64 * 16; i += 128) {
        int r = i >> 4, c4 = (i & 15) << 2;
        *(float4*)&Ks[r * AST + c4] = *(const float4*)&Qg[r * 64 + c4];
    }
    __syncthreads();
    uint32_t qf[8][4];
    #pragma unroll
    for (int ks = 0; ks < 8; ks++) {
        qf[ks][0] = __float_as_uint(Ks[(w*16+gl  ) * AST + ks*8 + cl    ]);
        qf[ks][1] = __float_as_uint(Ks[(w*16+gl+8) * AST + ks*8 + cl    ]);
        qf[ks][2] = __float_as_uint(Ks[(w*16+gl  ) * AST + ks*8 + cl + 4]);
        qf[ks][3] = __float_as_uint(Ks[(w*16+gl+8) * AST + ks*8 + cl + 4]);
    }

    float m0 = -1e30f, m1 = -1e30f, l0 = 0.f, l1 = 0.f;
    float oacc[8][4];
    #pragma unroll
    for (int nt = 0; nt < 8; nt++)
        #pragma unroll
        for (int r = 0; r < 4; r++) oacc[nt][r] = 0.f;

    for (int kt = 0; kt <= qt; kt++) {
        __syncthreads();
        const float* Kt = Kg + (size_t)kt * 64 * 64;
        const float* Vt = Vg + (size_t)kt * 64 * 64;
        for (int i = tid; i < 64 * 16; i += 128) {
            int r = i >> 4, c4 = (i & 15) << 2;
            *(float4*)&Ks[r * AST + c4] = *(const float4*)&Kt[r * 64 + c4];
            *(float4*)&Vs[r * VST + c4] = *(const float4*)&Vt[r * 64 + c4];
        }
        __syncthreads();

        float sacc[8][4];
        #pragma unroll
        for (int nt = 0; nt < 8; nt++)
            #pragma unroll
            for (int r = 0; r < 4; r++) sacc[nt][r] = 0.f;
        #pragma unroll
        for (int ks = 0; ks < 8; ks++) {
            #pragma unroll
            for (int nt = 0; nt < 8; nt++) {
                uint32_t bf[2];
                bf[0] = __float_as_uint(Ks[(nt*8+gl) * AST + ks*8 + cl    ]);
                bf[1] = __float_as_uint(Ks[(nt*8+gl) * AST + ks*8 + cl + 4]);
                mma8(sacc[nt], qf[ks], bf);
            }
        }
        #pragma unroll
        for (int nt = 0; nt < 8; nt++)
            #pragma unroll
            for (int r = 0; r < 4; r++) sacc[nt][r] *= 0.125f;
        if (kt == qt) {
            #pragma unroll
            for (int nt = 0; nt < 8; nt++)
                #pragma unroll
                for (int j = 0; j < 2; j++) {
                    int key = nt * 8 + 2 * cl + j;
                    if (key > w * 16 + gl)     sacc[nt][j]     = 1e-9f;
                    if (key > w * 16 + gl + 8) sacc[nt][2 + j] = 1e-9f;
                }
        }
        float rm0 = -1e30f, rm1 = -1e30f;
        #pragma unroll
        for (int nt = 0; nt < 8; nt++) {
            rm0 = fmaxf(rm0, fmaxf(sacc[nt][0], sacc[nt][1]));
            rm1 = fmaxf(rm1, fmaxf(sacc[nt][2], sacc[nt][3]));
        }
        rm0 = fmaxf(rm0, __shfl_xor_sync(0xffffffffu, rm0, 1));
        rm0 = fmaxf(rm0, __shfl_xor_sync(0xffffffffu, rm0, 2));
        rm1 = fmaxf(rm1, __shfl_xor_sync(0xffffffffu, rm1, 1));
        rm1 = fmaxf(rm1, __shfl_xor_sync(0xffffffffu, rm1, 2));
        float mn0 = fmaxf(m0, rm0), mn1 = fmaxf(m1, rm1);
        float a0 = __expf(m0 - mn0), a1 = __expf(m1 - mn1);
        m0 = mn0; m1 = mn1;
        float rs0 = 0.f, rs1 = 0.f;
        #pragma unroll
        for (int nt = 0; nt < 8; nt++) {
            float p0 = __expf(sacc[nt][0] - mn0);
            float p1 = __expf(sacc[nt][1] - mn0);
            float p2 = __expf(sacc[nt][2] - mn1);
            float p3 = __expf(sacc[nt][3] - mn1);
            rs0 += p0 + p1; rs1 += p2 + p3;
            *(float2*)&Ps[(w*16+gl  ) * AST + nt*8 + 2*cl] =
                make_float2(tf32r(p0), tf32r(p1));
            *(float2*)&Ps[(w*16+gl+8) * AST + nt*8 + 2*cl] =
                make_float2(tf32r(p2), tf32r(p3));
        }
        rs0 += __shfl_xor_sync(0xffffffffu, rs0, 1);
        rs0 += __shfl_xor_sync(0xffffffffu, rs0, 2);
        rs1 += __shfl_xor_sync(0xffffffffu, rs1, 1);
        rs1 += __shfl_xor_sync(0xffffffffu, rs1, 2);
        l0 = l0 * a0 + rs0;
        l1 = l1 * a1 + rs1;
        #pragma unroll
        for (int nt = 0; nt < 8; nt++) {
            oacc[nt][0] *= a0; oacc[nt][1] *= a0;
            oacc[nt][2] *= a1; oacc[nt][3] *= a1;
        }
        __syncwarp();

        #pragma unroll
        for (int ks = 0; ks < 8; ks++) {
            uint32_t af[4];
            af[0] = __float_as_uint(Ps[(w*16+gl  ) * AST + ks*8 + cl    ]);
            af[1] = __float_as_uint(Ps[(w*16+gl+8) * AST + ks*8 + cl    ]);
            af[2] = __float_as_uint(Ps[(w*16+gl  ) * AST + ks*8 + cl + 4]);
            af[3] = __float_as_uint(Ps[(w*16+gl+8) * AST + ks*8 + cl + 4]);
            #pragma unroll
            for (int nt = 0; nt < 8; nt++) {
                uint32_t bf[2];
                bf[0] = __float_as_uint(Vs[(ks*8+cl  ) * VST + nt*8 + gl]);
                bf[1] = __float_as_uint(Vs[(ks*8+cl+4) * VST + nt*8 + gl]);
                mma8(oacc[nt], af, bf);
            }
        }
    }
    __syncthreads();

    // ---- virtual masked tile: rows [(qt+1)*64, 1024) all score 1e-9 ----
    if (qt < 15) {
        const int mstart = (qt + 1) * 64;
        const float nmask = (float)(TT - mstart);
        {
            float ps = 0.f;
            const int col = tid & 63, seg = tid >> 6;
            for (int r = mstart + seg; r < TT; r += 2)
                ps += Vg[(size_t)r * 64 + col];
            Ps[seg * 64 + col] = ps;
        }
        __syncthreads();
        float nn0 = fmaxf(m0, 1e-9f), nn1 = fmaxf(m1, 1e-9f);
        float a0 = __expf(m0 - nn0), a1 = __expf(m1 - nn1);
        float e0 = __expf(1e-9f - nn0), e1 = __expf(1e-9f - nn1);
        l0 = l0 * a0 + nmask * e0;
        l1 = l1 * a1 + nmask * e1;
        #pragma unroll
        for (int nt = 0; nt < 8; nt++) {
            int col = nt * 8 + 2 * cl;
            float vs0 = Ps[col]     + Ps[64 + col];
            float vs1 = Ps[col + 1] + Ps[64 + col + 1];
            oacc[nt][0] = oacc[nt][0] * a0 + e0 * vs0;
            oacc[nt][1] = oacc[nt][1] * a0 + e0 * vs1;
            oacc[nt][2] = oacc[nt][2] * a1 + e1 * vs0;
            oacc[nt][3] = oacc[nt][3] * a1 + e1 * vs1;
        }
    }

    // ---- epilogue: x1 = x + y ----
    const float inv0 = 1.0f / l0, inv1 = 1.0f / l1;
    const size_t base0 = ((size_t)(b * TT + qg0 + w*16 + gl    )) * HH + head * HDIM;
    const size_t base1 = ((size_t)(b * TT + qg0 + w*16 + gl + 8)) * HH + head * HDIM;
    #pragma unroll
    for (int nt = 0; nt < 8; nt++) {
        int col = nt * 8 + 2 * cl;
        float2 xa = *(const float2*)&x[base0 + col];
        float2 xb = *(const float2*)&x[base1 + col];
        *(float2*)&x1[base0 + col] =
            make_float2(xa.x + oacc[nt][0] * inv0, xa.y + oacc[nt][1] * inv0);
        *(float2*)&x1[base1 + col] =
            make_float2(xb.x + oacc[nt][2] * inv1, xb.y + oacc[nt][3] * inv1);
    }
}

// ---------------- launch ----------------
extern "C" void kernel_launch(void* const* d_in, const int* in_sizes, int n_in,
                              void* d_out, int out_size)
{
    (void)in_sizes; (void)n_in; (void)out_size;
    const float* x    = (const float*)d_in[0];
    const float* ln1g = (const float*)d_in[1];
    const float* ln1b = (const float*)d_in[2];
    const float* ln2g = (const float*)d_in[3];
    const float* ln2b = (const float*)d_in[4];
    const float* Wq   = (const float*)d_in[5];
    const float* bq   = (const float*)d_in[6];
    const float* Wk   = (const float*)d_in[7];
    const float* bk   = (const float*)d_in[8];
    const float* Wv   = (const float*)d_in[9];
    const float* bv   = (const float*)d_in[10];
    const float* W1   = (const float*)d_in[11];
    const float* b1   = (const float*)d_in[12];
    const float* W2   = (const float*)d_in[13];
    const float* b2   = (const float*)d_in[14];
    float* out = (float*)d_out;

    float *hp, *q, *k, *v, *x1, *m1, *wqkv, *w1, *w2;
    cudaGetSymbolAddress((void**)&hp,   g_hp);
    cudaGetSymbolAddress((void**)&q,    g_q);
    cudaGetSymbolAddress((void**)&k,    g_k);
    cudaGetSymbolAddress((void**)&v,    g_v);
    cudaGetSymbolAddress((void**)&x1,   g_x1);
    cudaGetSymbolAddress((void**)&m1,   g_m1);
    cudaGetSymbolAddress((void**)&wqkv, g_wqkv);
    cudaGetSymbolAddress((void**)&w1,   g_w1);
    cudaGetSymbolAddress((void**)&w2,   g_w2);

    cudaFuncSetAttribute(attn_tc,
                         cudaFuncAttributeMaxDynamicSharedMemorySize, (int)ATTN_SMEM);
    cudaFuncSetAttribute(gemm_mma<EPI_QKV>,
                         cudaFuncAttributeMaxDynamicSharedMemorySize, GEMM_SMEM);
    cudaFuncSetAttribute(gemm_mma<EPI_GELU>,
                         cudaFuncAttributeMaxDynamicSharedMemorySize, GEMM_SMEM);
    cudaFuncSetAttribute(gemm_mma<EPI_RES>,
                         cudaFuncAttributeMaxDynamicSharedMemorySize, GEMM_SMEM);

    // fused weight prep (all 5 weights, one launch)
    prep_all<<<2816, 256>>>(Wq, Wk, Wv, W1, W2, wqkv, w1, w2);

    // LN1 -> hp (A-fragment order)
    ln_kernel<<<ROWS, 256>>>(x, ln1g, ln1b, hp);
    // fused QKV projection (tf32-rounded stores): N=3072
    gemm_mma<EPI_QKV><<<dim3(3 * HH / 128, ROWS / 128), 128, GEMM_SMEM>>>(
        hp, wqkv, bq, bk, bv, nullptr, q, k, v, 3 * HH, HH);
    // tensor-core attention (Q-tile 64, R14 config) + residual
    attn_tc<<<dim3(TT / 64, NHEAD, BB), 128, ATTN_SMEM>>>(q, k, v, x, x1);
    // LN2 -> hp (A-fragment order)
    ln_kernel<<<ROWS, 256>>>(x1, ln2g, ln2b, hp);
    // MLP: W1 gemm writes m1 in A-fragment order; W2 gemm reads it back
    gemm_mma<EPI_GELU><<<dim3(4 * HH / 128, ROWS / 128), 128, GEMM_SMEM>>>(
        hp, w1, b1, nullptr, nullptr, nullptr, m1, nullptr, nullptr, 4 * HH, HH);
    gemm_mma<EPI_RES><<<dim3(HH / 128, ROWS / 128), 128, GEMM_SMEM>>>(
        m1, w2, b2, nullptr, nullptr, x1, out, nullptr, nullptr, HH, 4 * HH);
}